// round 7
// baseline (speedup 1.0000x reference)
#include <cuda_runtime.h>

// Problem constants
#define E_ 4
#define B_ 128
#define Q_ 900
#define C_ 256
#define H_ 16
#define QC_ (Q_ * C_)          // 230400
#define QC4_ (QC_ / 4)         // 57600 float4 per b
#define TOTAL4_ (B_ * QC4_)    // 7,372,800 float4 total

// Persistent launch config: one resident wave.
#define THR_ 128
#define NBLK_ 1440             // <= 148 SMs * 12 blocks/SM (launch_bounds)
#define STRIDE_ (NBLK_ * THR_) // 184,320
#define NITER_ (TOTAL4_ / STRIDE_)  // 40, exact

// Phase-1 jobs: (e,b) row split in 2 halves of 450 q's.
#define SPLIT_ 2
#define QHALF_ 450
#define NJOBS_ (E_ * B_ * SPLIT_)   // 1024 <= NBLK_

// Scratch (no device mallocs allowed)
__device__ float g_partial[NJOBS_];      // per (e,b,half) partial sums
__device__ int   g_idx[B_ * 2];          // top-2 indices per b
__device__ float g_w[B_ * 2];            // renormalized top-2 weights per b
__device__ unsigned int g_done;          // arrival counter (reset each replay)
__device__ volatile unsigned int g_epoch; // monotonic epoch (never reset)

__global__ void __launch_bounds__(THR_, 12) moe_persistent_kernel(
    const float* __restrict__ logits,
    const float* __restrict__ W1,
    const float* __restrict__ b1,
    const float* __restrict__ W2,
    const float* __restrict__ b2,
    float* __restrict__ out) {

    const int tid = threadIdx.x;
    const int blk = blockIdx.x;

    // ---- read epoch BEFORE arrival (ordering vs. the gate's bump) ----
    __shared__ unsigned int s_e0;
    __shared__ bool s_last;
    if (tid == 0) s_e0 = g_epoch;
    __syncthreads();                 // compiler+thread barrier: e0 read first
    const unsigned int e0 = s_e0;

    // ================= Phase 1: scattered class-0 partial sums ===========
    if (blk < NJOBS_) {
        int row  = blk >> 1;         // e*B + b
        int part = blk & 1;
        const float* base = logits + (size_t)row * QC_ + (size_t)part * QHALF_ * C_;

        float v = 0.0f;
        #pragma unroll
        for (int k = 0; k < 4; k++) {
            int ql = tid + k * THR_;
            if (ql < QHALF_)
                v += __ldg(base + (size_t)ql * C_);
        }
        #pragma unroll
        for (int o = 16; o > 0; o >>= 1)
            v += __shfl_down_sync(0xffffffffu, v, o);

        __shared__ float ws[4];
        if ((tid & 31) == 0) ws[tid >> 5] = v;
        __syncthreads();
        if (tid == 0)
            g_partial[blk] = ws[0] + ws[1] + ws[2] + ws[3];
    }

    // ---- arrival counter: ALL blocks arrive; last one runs the gate ----
    if (tid == 0) {
        __threadfence();
        unsigned int n = atomicAdd(&g_done, 1u);
        s_last = (n == NBLK_ - 1);
        if (s_last) g_done = 0;      // reset for next graph replay
    }
    __syncthreads();

    if (s_last) {
        // ============ Gate: one thread per b (128 threads) ==============
        int b = tid;

        float p[E_];
        #pragma unroll
        for (int e = 0; e < E_; e++) {
            float t = 0.0f;
            #pragma unroll
            for (int s = 0; s < SPLIT_; s++)
                t += g_partial[(e * B_ + b) * SPLIT_ + s];
            float m = t * (1.0f / (float)Q_);
            p[e] = 1.0f / (1.0f + expf(-m));
        }

        float h[H_];
        #pragma unroll
        for (int j = 0; j < H_; j++) {
            float a = b1[j];
            #pragma unroll
            for (int e = 0; e < E_; e++) a += p[e] * W1[e * H_ + j];
            h[j] = fmaxf(a, 0.0f);
        }

        float z[E_];
        #pragma unroll
        for (int e = 0; e < E_; e++) {
            float a = b2[e];
            #pragma unroll
            for (int j = 0; j < H_; j++) a += h[j] * W2[j * E_ + e];
            z[e] = a;
        }

        float m = fmaxf(fmaxf(z[0], z[1]), fmaxf(z[2], z[3]));
        float w[E_], s = 0.0f;
        #pragma unroll
        for (int e = 0; e < E_; e++) { w[e] = expf(z[e] - m); s += w[e]; }
        float inv = 1.0f / s;
        #pragma unroll
        for (int e = 0; e < E_; e++) w[e] *= inv;

        int i0 = 0;
        #pragma unroll
        for (int e = 1; e < E_; e++) if (w[e] > w[i0]) i0 = e;
        int i1 = -1;
        #pragma unroll
        for (int e = 0; e < E_; e++) {
            if (e == i0) continue;
            if (i1 < 0 || w[e] > w[i1]) i1 = e;
        }

        float ms = w[i0] + w[i1];
        float rn = 1.0f / (ms + 1e-8f);
        float n0 = w[i0] * rn;
        float n1 = w[i1] * rn;

        g_idx[b * 2 + 0] = i0;
        g_idx[b * 2 + 1] = i1;
        g_w[b * 2 + 0] = n0;
        g_w[b * 2 + 1] = n1;

        // Output tail: [combined | final_pred | norm_w | expert_probs | top_idx]
        float* fp = out + (size_t)B_ * QC_;
        float* nw = fp + B_;
        float* ep = nw + B_ * E_;
        float* ti = ep + B_ * E_;

        fp[b] = n0 * p[i0] + n1 * p[i1];
        #pragma unroll
        for (int e = 0; e < E_; e++) {
            nw[b * E_ + e] = (e == i0) ? n0 : ((e == i1) ? n1 : 0.0f);
            ep[b * E_ + e] = p[e];
        }
        ti[b * 2 + 0] = (float)i0;
        ti[b * 2 + 1] = (float)i1;

        __syncthreads();
        if (tid == 0) {
            __threadfence();         // publish gate results before epoch bump
            g_epoch = e0 + 1u;
        }
    } else {
        // ---- spin until gate published (bounded: fail visibly, not hang) --
        if (tid == 0) {
            long sp = 0;
            while (g_epoch == e0 && sp < (1L << 28)) { __nanosleep(64); sp++; }
        }
        __syncthreads();
        __threadfence();             // acquire: see g_idx/g_w
    }

    // ================= Phase 2: streaming combine ========================
    // Stage gate tables in smem (avoid per-iter global loads).
    __shared__ int   s_j0[B_], s_j1[B_];
    __shared__ float s_w0[B_], s_w1[B_];
    s_j0[tid] = g_idx[tid * 2 + 0];
    s_j1[tid] = g_idx[tid * 2 + 1];
    s_w0[tid] = g_w[tid * 2 + 0];
    s_w1[tid] = g_w[tid * 2 + 1];
    __syncthreads();

    const float4* src = (const float4*)logits;
    float4* dst = (float4*)out;
    int base = blk * THR_ + tid;

    #pragma unroll 4
    for (int it = 0; it < NITER_; it++) {
        int i = base + it * STRIDE_;
        int b = i / QC4_;
        int off = i - b * QC4_;
        int j0 = s_j0[b], j1 = s_j1[b];
        float w0 = s_w0[b], w1 = s_w1[b];

        float4 x = __ldcs(src + (size_t)(j0 * B_ + b) * QC4_ + off);
        float4 y = __ldcs(src + (size_t)(j1 * B_ + b) * QC4_ + off);
        float4 r;
        r.x = w0 * x.x + w1 * y.x;
        r.y = w0 * x.y + w1 * y.y;
        r.z = w0 * x.z + w1 * y.z;
        r.w = w0 * x.w + w1 * y.w;
        __stcs(dst + i, r);
    }
}

extern "C" void kernel_launch(void* const* d_in, const int* in_sizes, int n_in,
                              void* d_out, int out_size) {
    const float* logits = (const float*)d_in[0];
    const float* W1     = (const float*)d_in[1];
    const float* b1     = (const float*)d_in[2];
    const float* W2     = (const float*)d_in[3];
    const float* b2     = (const float*)d_in[4];
    float* out = (float*)d_out;

    moe_persistent_kernel<<<NBLK_, THR_>>>(logits, W1, b1, W2, b2, out);
}

// round 9
// speedup vs baseline: 1.0363x; 1.0363x over previous
#include <cuda_runtime.h>
#include <cuda_device_runtime_api.h>

// Problem constants
#define E_ 4
#define B_ 128
#define Q_ 900
#define C_ 256
#define H_ 16
#define QC_ (Q_ * C_)          // 230400
#define QC4_ (QC_ / 4)         // 57600 float4 per (b)

#define SPLIT_ 8               // blocks per (e,b) row in probs pass
#define QCHUNK_ 113            // ceil(900/8)
#define NPROBS_ (E_ * B_ * SPLIT_)   // 4096 blocks

// Combine config: grid (75, B), 256 threads, 3 float4 per thread
#define CB_THREADS_ 256
#define CB_ITERS_ 3
#define CB_BLOCKSX_ (QC4_ / (CB_THREADS_ * CB_ITERS_))   // 75
#define CB_CHUNK_ (CB_THREADS_ * CB_ITERS_)              // 768

// Scratch (no device mallocs allowed)
__device__ float g_partial[NPROBS_];   // partial q-sums per (e,b,part)
__device__ int   g_idx[B_ * 2];        // top-2 indices per b
__device__ float g_w[B_ * 2];          // renormalized top-2 weights per b
__device__ unsigned int g_done;        // last-block-done counter

// ---------------------------------------------------------------------------
// Kernel A (PDL primary): partial class-0 sums + (last block) gate.
// Triggers programmatic launch of the combine kernel immediately so the
// 9600-block secondary grid is scheduled while this kernel drains DRAM.
// ---------------------------------------------------------------------------
__global__ void __launch_bounds__(128) probs_gate_kernel(
    const float* __restrict__ logits,
    const float* __restrict__ W1,
    const float* __restrict__ b1,
    const float* __restrict__ W2,
    const float* __restrict__ b2,
    float* __restrict__ out) {

    // Let the dependent combine grid start launching right away; it blocks
    // on cudaGridDependencySynchronize() (full-grid completion) before
    // consuming any of our results.
    cudaTriggerProgrammaticLaunchCompletion();

    int blk  = blockIdx.x;
    int row  = blk / SPLIT_;         // e*B + b
    int part = blk % SPLIT_;

    int q = part * QCHUNK_ + threadIdx.x;
    float v = 0.0f;
    if (threadIdx.x < QCHUNK_ && q < Q_)
        v = __ldg(logits + (size_t)row * QC_ + (size_t)q * C_);

    #pragma unroll
    for (int o = 16; o > 0; o >>= 1)
        v += __shfl_down_sync(0xffffffffu, v, o);

    __shared__ float ws[4];
    __shared__ bool is_last;
    int lane = threadIdx.x & 31;
    int wid  = threadIdx.x >> 5;
    if (lane == 0) ws[wid] = v;
    __syncthreads();
    if (threadIdx.x == 0) {
        g_partial[row * SPLIT_ + part] = ws[0] + ws[1] + ws[2] + ws[3];
        __threadfence();
        unsigned int n = atomicAdd(&g_done, 1u);
        is_last = (n == NPROBS_ - 1);
        if (is_last) g_done = 0;     // reset for next graph replay
    }
    __syncthreads();
    if (!is_last) return;

    // ---- gate: one thread per b (128 threads) ----
    int b = threadIdx.x;

    float p[E_];
    #pragma unroll
    for (int e = 0; e < E_; e++) {
        float t = 0.0f;
        #pragma unroll
        for (int s = 0; s < SPLIT_; s++)
            t += g_partial[(e * B_ + b) * SPLIT_ + s];
        float m = t * (1.0f / (float)Q_);
        p[e] = 1.0f / (1.0f + expf(-m));
    }

    float h[H_];
    #pragma unroll
    for (int j = 0; j < H_; j++) {
        float a = b1[j];
        #pragma unroll
        for (int e = 0; e < E_; e++) a += p[e] * W1[e * H_ + j];
        h[j] = fmaxf(a, 0.0f);
    }

    float z[E_];
    #pragma unroll
    for (int e = 0; e < E_; e++) {
        float a = b2[e];
        #pragma unroll
        for (int j = 0; j < H_; j++) a += h[j] * W2[j * E_ + e];
        z[e] = a;
    }

    float m = fmaxf(fmaxf(z[0], z[1]), fmaxf(z[2], z[3]));
    float w[E_], s = 0.0f;
    #pragma unroll
    for (int e = 0; e < E_; e++) { w[e] = expf(z[e] - m); s += w[e]; }
    float inv = 1.0f / s;
    #pragma unroll
    for (int e = 0; e < E_; e++) w[e] *= inv;

    int i0 = 0;
    #pragma unroll
    for (int e = 1; e < E_; e++) if (w[e] > w[i0]) i0 = e;
    int i1 = -1;
    #pragma unroll
    for (int e = 0; e < E_; e++) {
        if (e == i0) continue;
        if (i1 < 0 || w[e] > w[i1]) i1 = e;
    }

    float ms = w[i0] + w[i1];
    float rn = 1.0f / (ms + 1e-8f);
    float n0 = w[i0] * rn;
    float n1 = w[i1] * rn;

    g_idx[b * 2 + 0] = i0;
    g_idx[b * 2 + 1] = i1;
    g_w[b * 2 + 0] = n0;
    g_w[b * 2 + 1] = n1;

    // Output tail layout: [combined | final_pred | norm_w | expert_probs | top_idx]
    float* fp = out + (size_t)B_ * QC_;
    float* nw = fp + B_;
    float* ep = nw + B_ * E_;
    float* ti = ep + B_ * E_;

    fp[b] = n0 * p[i0] + n1 * p[i1];
    #pragma unroll
    for (int e = 0; e < E_; e++) {
        nw[b * E_ + e] = (e == i0) ? n0 : ((e == i1) ? n1 : 0.0f);
        ep[b * E_ + e] = p[e];
    }
    ti[b * 2 + 0] = (float)i0;
    ti[b * 2 + 1] = (float)i1;
}

// ---------------------------------------------------------------------------
// Kernel C (PDL secondary): combined[b,q,c] = n0*logits[i0,b,q,c] + n1*...
// grid (75, B): b uniform per block, 3 float4 per thread, loads front-
// batched, streaming loads/stores. Blocks launch while the primary is still
// running; cudaGridDependencySynchronize() gates the first dependent read.
// ---------------------------------------------------------------------------
__global__ void __launch_bounds__(CB_THREADS_) combine_kernel(
    const float* __restrict__ logits, float* __restrict__ out) {
    int b = blockIdx.y;
    int base = blockIdx.x * CB_CHUNK_ + threadIdx.x;   // within [0, QC4)

    const float4* src = (const float4*)logits;
    float4* dst = (float4*)out;
    float4* o = dst + (size_t)b * QC4_;

    // Wait for the primary grid (probs + gate) to fully complete.
    cudaGridDependencySynchronize();

    int i0 = g_idx[b * 2 + 0];
    int i1 = g_idx[b * 2 + 1];
    float w0 = g_w[b * 2 + 0];
    float w1 = g_w[b * 2 + 1];

    const float4* a0 = src + (size_t)(i0 * B_ + b) * QC4_;
    const float4* a1 = src + (size_t)(i1 * B_ + b) * QC4_;

    float4 x[CB_ITERS_], y[CB_ITERS_];
    #pragma unroll
    for (int k = 0; k < CB_ITERS_; k++)
        x[k] = __ldcs(a0 + base + k * CB_THREADS_);
    #pragma unroll
    for (int k = 0; k < CB_ITERS_; k++)
        y[k] = __ldcs(a1 + base + k * CB_THREADS_);

    #pragma unroll
    for (int k = 0; k < CB_ITERS_; k++) {
        float4 r;
        r.x = w0 * x[k].x + w1 * y[k].x;
        r.y = w0 * x[k].y + w1 * y[k].y;
        r.z = w0 * x[k].z + w1 * y[k].z;
        r.w = w0 * x[k].w + w1 * y[k].w;
        __stcs(o + base + k * CB_THREADS_, r);
    }
}

extern "C" void kernel_launch(void* const* d_in, const int* in_sizes, int n_in,
                              void* d_out, int out_size) {
    const float* logits = (const float*)d_in[0];
    const float* W1     = (const float*)d_in[1];
    const float* b1     = (const float*)d_in[2];
    const float* W2     = (const float*)d_in[3];
    const float* b2     = (const float*)d_in[4];
    float* out = (float*)d_out;

    probs_gate_kernel<<<NPROBS_, 128>>>(logits, W1, b1, W2, b2, out);

    // Combine with programmatic dependent launch: overlap grid launch +
    // prologue with the primary's DRAM drain.
    cudaLaunchConfig_t cfg = {};
    cfg.gridDim = dim3(CB_BLOCKSX_, B_, 1);
    cfg.blockDim = dim3(CB_THREADS_, 1, 1);
    cfg.dynamicSmemBytes = 0;
    cfg.stream = 0;
    cudaLaunchAttribute attrs[1];
    attrs[0].id = cudaLaunchAttributeProgrammaticStreamSerialization;
    attrs[0].val.programmaticStreamSerializationAllowed = 1;
    cfg.attrs = attrs;
    cfg.numAttrs = 1;
    cudaLaunchKernelEx(&cfg, combine_kernel, logits, out);
}

// round 10
// speedup vs baseline: 1.0592x; 1.0221x over previous
#include <cuda_runtime.h>

// Problem constants
#define E_ 4
#define B_ 128
#define Q_ 900
#define C_ 256
#define H_ 16
#define QC_ (Q_ * C_)          // 230400
#define QC4_ (QC_ / 4)         // 57600 float4 per (b)

#define SPLIT_ 8               // blocks per (e,b) row in probs pass
#define QCHUNK_ 113            // ceil(900/8)
#define NPROBS_ (E_ * B_ * SPLIT_)   // 4096 blocks

// Combine config: grid (75, B), 256 threads, 3 float4 per thread
#define CB_THREADS_ 256
#define CB_ITERS_ 3
#define CB_BLOCKSX_ (QC4_ / (CB_THREADS_ * CB_ITERS_))   // 75
#define CB_CHUNK_ (CB_THREADS_ * CB_ITERS_)              // 768

// Scratch (no device mallocs allowed)
__device__ float g_partial[NPROBS_];   // partial q-sums per (e,b,part)
__device__ int   g_idx[B_ * 2];        // top-2 indices per b
__device__ float g_w[B_ * 2];          // renormalized top-2 weights per b

// L2-only sector-granular load (avoid nc/tex-path 128B line fill).
__device__ __forceinline__ float ldcg(const float* p) {
    float v;
    asm volatile("ld.global.cg.f32 %0, [%1];" : "=f"(v) : "l"(p));
    return v;
}

// ---------------------------------------------------------------------------
// Kernel A: partial sums of class-0 logits over q.
// grid = E*B*SPLIT blocks of 128 threads; each thread does <=1 scattered load
// via ld.global.cg (32B-sector DRAM fill instead of 128B line fill).
// ---------------------------------------------------------------------------
__global__ void __launch_bounds__(128) probs_partial_kernel(
    const float* __restrict__ logits) {
    int blk  = blockIdx.x;
    int row  = blk / SPLIT_;         // e*B + b
    int part = blk % SPLIT_;

    int q = part * QCHUNK_ + threadIdx.x;
    float v = 0.0f;
    if (threadIdx.x < QCHUNK_ && q < Q_)
        v = ldcg(logits + (size_t)row * QC_ + (size_t)q * C_);

    #pragma unroll
    for (int o = 16; o > 0; o >>= 1)
        v += __shfl_down_sync(0xffffffffu, v, o);

    __shared__ float ws[4];
    int lane = threadIdx.x & 31;
    int wid  = threadIdx.x >> 5;
    if (lane == 0) ws[wid] = v;
    __syncthreads();
    if (threadIdx.x == 0)
        g_partial[row * SPLIT_ + part] = ws[0] + ws[1] + ws[2] + ws[3];
}

// ---------------------------------------------------------------------------
// Kernel B: finish reduction -> sigmoid -> gating MLP + softmax + top-2.
// One thread per b. Also writes the small output tails.
// ---------------------------------------------------------------------------
__global__ void gate_kernel(const float* __restrict__ W1,
                            const float* __restrict__ b1,
                            const float* __restrict__ W2,
                            const float* __restrict__ b2,
                            float* __restrict__ out) {
    int b = threadIdx.x;
    if (b >= B_) return;

    float p[E_];
    #pragma unroll
    for (int e = 0; e < E_; e++) {
        float t = 0.0f;
        #pragma unroll
        for (int s = 0; s < SPLIT_; s++)
            t += g_partial[(e * B_ + b) * SPLIT_ + s];
        float m = t * (1.0f / (float)Q_);
        p[e] = 1.0f / (1.0f + expf(-m));
    }

    float h[H_];
    #pragma unroll
    for (int j = 0; j < H_; j++) {
        float a = b1[j];
        #pragma unroll
        for (int e = 0; e < E_; e++) a += p[e] * W1[e * H_ + j];
        h[j] = fmaxf(a, 0.0f);
    }

    float z[E_];
    #pragma unroll
    for (int e = 0; e < E_; e++) {
        float a = b2[e];
        #pragma unroll
        for (int j = 0; j < H_; j++) a += h[j] * W2[j * E_ + e];
        z[e] = a;
    }

    float m = fmaxf(fmaxf(z[0], z[1]), fmaxf(z[2], z[3]));
    float w[E_], s = 0.0f;
    #pragma unroll
    for (int e = 0; e < E_; e++) { w[e] = expf(z[e] - m); s += w[e]; }
    float inv = 1.0f / s;
    #pragma unroll
    for (int e = 0; e < E_; e++) w[e] *= inv;

    int i0 = 0;
    #pragma unroll
    for (int e = 1; e < E_; e++) if (w[e] > w[i0]) i0 = e;
    int i1 = -1;
    #pragma unroll
    for (int e = 0; e < E_; e++) {
        if (e == i0) continue;
        if (i1 < 0 || w[e] > w[i1]) i1 = e;
    }

    float ms = w[i0] + w[i1];
    float rn = 1.0f / (ms + 1e-8f);
    float n0 = w[i0] * rn;
    float n1 = w[i1] * rn;

    g_idx[b * 2 + 0] = i0;
    g_idx[b * 2 + 1] = i1;
    g_w[b * 2 + 0] = n0;
    g_w[b * 2 + 1] = n1;

    // Output tail layout: [combined | final_pred | norm_w | expert_probs | top_idx]
    float* fp = out + (size_t)B_ * QC_;
    float* nw = fp + B_;
    float* ep = nw + B_ * E_;
    float* ti = ep + B_ * E_;

    fp[b] = n0 * p[i0] + n1 * p[i1];
    #pragma unroll
    for (int e = 0; e < E_; e++) {
        nw[b * E_ + e] = (e == i0) ? n0 : ((e == i1) ? n1 : 0.0f);
        ep[b * E_ + e] = p[e];
    }
    ti[b * 2 + 0] = (float)i0;
    ti[b * 2 + 1] = (float)i1;
}

// ---------------------------------------------------------------------------
// Kernel C: combined[b,q,c] = n0 * logits[i0,b,q,c] + n1 * logits[i1,b,q,c]
// grid (75, B): b uniform per block, 3 float4 per thread, loads front-
// batched, streaming loads/stores. 75*256*3 = 57600 float4 per b (exact).
// ---------------------------------------------------------------------------
__global__ void __launch_bounds__(CB_THREADS_) combine_kernel(
    const float* __restrict__ logits, float* __restrict__ out) {
    int b = blockIdx.y;
    int base = blockIdx.x * CB_CHUNK_ + threadIdx.x;   // within [0, QC4)

    int i0 = g_idx[b * 2 + 0];
    int i1 = g_idx[b * 2 + 1];
    float w0 = g_w[b * 2 + 0];
    float w1 = g_w[b * 2 + 1];

    const float4* a0 = (const float4*)logits + (size_t)(i0 * B_ + b) * QC4_;
    const float4* a1 = (const float4*)logits + (size_t)(i1 * B_ + b) * QC4_;
    float4* o = (float4*)out + (size_t)b * QC4_;

    float4 x[CB_ITERS_], y[CB_ITERS_];
    #pragma unroll
    for (int k = 0; k < CB_ITERS_; k++)
        x[k] = __ldcs(a0 + base + k * CB_THREADS_);
    #pragma unroll
    for (int k = 0; k < CB_ITERS_; k++)
        y[k] = __ldcs(a1 + base + k * CB_THREADS_);

    #pragma unroll
    for (int k = 0; k < CB_ITERS_; k++) {
        float4 r;
        r.x = w0 * x[k].x + w1 * y[k].x;
        r.y = w0 * x[k].y + w1 * y[k].y;
        r.z = w0 * x[k].z + w1 * y[k].z;
        r.w = w0 * x[k].w + w1 * y[k].w;
        __stcs(o + base + k * CB_THREADS_, r);
    }
}

extern "C" void kernel_launch(void* const* d_in, const int* in_sizes, int n_in,
                              void* d_out, int out_size) {
    const float* logits = (const float*)d_in[0];
    const float* W1     = (const float*)d_in[1];
    const float* b1     = (const float*)d_in[2];
    const float* W2     = (const float*)d_in[3];
    const float* b2     = (const float*)d_in[4];
    float* out = (float*)d_out;

    probs_partial_kernel<<<NPROBS_, 128>>>(logits);
    gate_kernel<<<1, B_>>>(W1, b1, W2, b2, out);
    combine_kernel<<<dim3(CB_BLOCKSX_, B_), CB_THREADS_>>>(logits, out);
}